// round 2
// baseline (speedup 1.0000x reference)
#include <cuda_runtime.h>
#include <math.h>

#define NLAYER 6
#define HEADS  12
#define DMODEL 384
#define DKH    32
#define DFF    1536
#define SEQ    512
#define BATCH  64
#define NTOK   (BATCH*SEQ)   /* 32768 */

// ---------------- scratch (device globals; no allocs allowed) ----------------
__device__ float g_x[NTOK*DMODEL];
__device__ float g_q[NTOK*DMODEL];
__device__ float g_k[NTOK*DMODEL];
__device__ float g_v[NTOK*DMODEL];
__device__ float g_o[NTOK*DMODEL];
__device__ float g_t[NTOK*DMODEL];
__device__ float g_beta[NTOK*HEADS];
__device__ float g_h[NTOK*DFF];

// ---------------- helpers ----------------
__device__ __forceinline__ float warpSum(float v) {
#pragma unroll
    for (int o = 16; o > 0; o >>= 1) v += __shfl_xor_sync(0xffffffffu, v, o);
    return v;
}

__device__ __forceinline__ float gelu_t(float x) {
    // jax.nn.gelu default (approximate=True, tanh form)
    float u = 0.7978845608028654f * (x + 0.044715f * x * x * x);
    return 0.5f * x * (1.0f + tanhf(u));
}

__device__ __forceinline__ float sigm(float x) {
    return 1.0f / (1.0f + expf(-x));
}

// ---------------- embedding + layernorm ----------------
__global__ void embed_ln_kernel(const int* __restrict__ ids,
                                const float* __restrict__ we,
                                const float* __restrict__ pe,
                                const float* __restrict__ te,
                                const float* __restrict__ g,
                                const float* __restrict__ bta) {
    int token = blockIdx.x;
    int l = token & (SEQ - 1);
    int id = ids[token];
    int tid = threadIdx.x;
    __shared__ float red[4];

    float v[3];
    float s = 0.f;
#pragma unroll
    for (int j = 0; j < 3; j++) {
        int d = tid + j * 128;
        float val = we[id * DMODEL + d] + pe[l * DMODEL + d] + te[d];
        v[j] = val; s += val;
    }
    s = warpSum(s);
    if ((tid & 31) == 0) red[tid >> 5] = s;
    __syncthreads();
    float mean = (red[0] + red[1] + red[2] + red[3]) * (1.0f / DMODEL);
    float s2 = 0.f;
#pragma unroll
    for (int j = 0; j < 3; j++) { float d0 = v[j] - mean; s2 += d0 * d0; }
    s2 = warpSum(s2);
    __syncthreads();
    if ((tid & 31) == 0) red[tid >> 5] = s2;
    __syncthreads();
    float var = (red[0] + red[1] + red[2] + red[3]) * (1.0f / DMODEL);
    float inv = rsqrtf(var + 1e-12f);
#pragma unroll
    for (int j = 0; j < 3; j++) {
        int d = tid + j * 128;
        g_x[token * DMODEL + d] = (v[j] - mean) * inv * g[d] + bta[d];
    }
}

// ---------------- residual add + layernorm (in-place on x) ----------------
__global__ void add_ln_kernel(float* __restrict__ x,
                              const float* __restrict__ t,
                              const float* __restrict__ g,
                              const float* __restrict__ bta) {
    int token = blockIdx.x;
    int tid = threadIdx.x;
    __shared__ float red[4];
    float v[3];
    float s = 0.f;
#pragma unroll
    for (int j = 0; j < 3; j++) {
        int d = tid + j * 128;
        float val = x[token * DMODEL + d] + t[token * DMODEL + d];
        v[j] = val; s += val;
    }
    s = warpSum(s);
    if ((tid & 31) == 0) red[tid >> 5] = s;
    __syncthreads();
    float mean = (red[0] + red[1] + red[2] + red[3]) * (1.0f / DMODEL);
    float s2 = 0.f;
#pragma unroll
    for (int j = 0; j < 3; j++) { float d0 = v[j] - mean; s2 += d0 * d0; }
    s2 = warpSum(s2);
    __syncthreads();
    if ((tid & 31) == 0) red[tid >> 5] = s2;
    __syncthreads();
    float var = (red[0] + red[1] + red[2] + red[3]) * (1.0f / DMODEL);
    float inv = rsqrtf(var + 1e-12f);
#pragma unroll
    for (int j = 0; j < 3; j++) {
        int d = tid + j * 128;
        x[token * DMODEL + d] = (v[j] - mean) * inv * g[d] + bta[d];
    }
}

// ---------------- SGEMM: C[M,N] = A[M,K] @ B[K,N] + bias, optional double-gelu ----------------
// BM=128 BN=128 BK=16, 256 threads, 8x8 per-thread tile
template<int EPI>
__global__ void __launch_bounds__(256) sgemm_kernel(const float* __restrict__ A,
                                                    const float* __restrict__ B,
                                                    const float* __restrict__ bias,
                                                    float* __restrict__ C,
                                                    int M, int N, int K) {
    const int BM = 128, BN = 128, BK = 16, TM = 8, TN = 8;
    __shared__ float As[BK][BM + 4];
    __shared__ float Bs[BK][BN];

    int tid = threadIdx.x;
    int bm = blockIdx.y * BM;
    int bn = blockIdx.x * BN;
    int tx = tid & 15, ty = tid >> 4;

    float acc[TM][TN];
#pragma unroll
    for (int i = 0; i < TM; i++)
#pragma unroll
        for (int j = 0; j < TN; j++) acc[i][j] = 0.f;

    for (int k0 = 0; k0 < K; k0 += BK) {
        // load A tile (128x16): 512 float4, 2 per thread
#pragma unroll
        for (int it = 0; it < 2; it++) {
            int f = tid + it * 256;          // 0..511
            int m = f >> 2;                  // 0..127
            int kk = (f & 3) * 4;            // 0,4,8,12
            float4 av = *(const float4*)(A + (size_t)(bm + m) * K + k0 + kk);
            As[kk + 0][m] = av.x;
            As[kk + 1][m] = av.y;
            As[kk + 2][m] = av.z;
            As[kk + 3][m] = av.w;
        }
        // load B tile (16x128): 512 float4, 2 per thread
#pragma unroll
        for (int it = 0; it < 2; it++) {
            int f = tid + it * 256;
            int kk = f >> 5;                 // 0..15
            int n = (f & 31) * 4;
            float4 bv = *(const float4*)(B + (size_t)(k0 + kk) * N + bn + n);
            *(float4*)&Bs[kk][n] = bv;
        }
        __syncthreads();
#pragma unroll
        for (int kk = 0; kk < BK; kk++) {
            float ra[TM], rb[TN];
#pragma unroll
            for (int i = 0; i < TM; i++) ra[i] = As[kk][ty * TM + i];
#pragma unroll
            for (int j = 0; j < TN; j++) rb[j] = Bs[kk][tx * TN + j];
#pragma unroll
            for (int i = 0; i < TM; i++)
#pragma unroll
                for (int j = 0; j < TN; j++) acc[i][j] += ra[i] * rb[j];
        }
        __syncthreads();
    }

#pragma unroll
    for (int i = 0; i < TM; i++) {
        int m = bm + ty * TM + i;
#pragma unroll
        for (int j = 0; j < TN; j += 4) {
            int n = bn + tx * TN + j;
            float4 o;
            float a0 = acc[i][j + 0] + bias[n + 0];
            float a1 = acc[i][j + 1] + bias[n + 1];
            float a2 = acc[i][j + 2] + bias[n + 2];
            float a3 = acc[i][j + 3] + bias[n + 3];
            if (EPI == 1) {
                a0 = gelu_t(gelu_t(a0)); a1 = gelu_t(gelu_t(a1));
                a2 = gelu_t(gelu_t(a2)); a3 = gelu_t(gelu_t(a3));
            }
            o.x = a0; o.y = a1; o.z = a2; o.w = a3;
            *(float4*)&C[(size_t)m * N + n] = o;
        }
    }
}

// ---------------- per-(token,head) l2 norm (+ optional mask multiply) ----------------
__global__ void qknorm_kernel(float* __restrict__ t, const float* __restrict__ mask, int use_mask) {
    int token = blockIdx.x;
    int h = threadIdx.x >> 5;
    int lane = threadIdx.x & 31;
    int idx = token * DMODEL + h * DKH + lane;
    float val = t[idx];
    float ss = warpSum(val * val);
    float inv = 1.0f / (sqrtf(ss) + 1e-6f);
    float m = use_mask ? mask[token] : 1.0f;
    t[idx] = val * inv * m;
}

// ---------------- beta = sigmoid(x @ Wb) * mask ----------------
__global__ void beta_kernel(const float* __restrict__ x, const float* __restrict__ Wb,
                            const float* __restrict__ mask) {
    int token = blockIdx.x;
    int h = threadIdx.x >> 5;
    int lane = threadIdx.x & 31;
    const float* xr = x + (size_t)token * DMODEL;
    float s = 0.f;
#pragma unroll
    for (int k = lane; k < DMODEL; k += 32) s += xr[k] * Wb[k * HEADS + h];
    s = warpSum(s);
    if (lane == 0) g_beta[token * HEADS + h] = sigm(s) * mask[token];
}

// ---------------- delta recurrence: one warp per (b,h) ----------------
__global__ void delta_kernel(const float* __restrict__ decay_f,
                             const float* __restrict__ decay_s,
                             int layer) {
    int bh = blockIdx.x;
    int b = bh / HEADS;
    int h = bh % HEADS;
    int lane = threadIdx.x;

    float gf = sigm(decay_f[layer * HEADS + h]);
    float gs = sigm(decay_s[layer * HEADS + h]);

    float Sf[DKH], Ss[DKH];
#pragma unroll
    for (int j = 0; j < DKH; j++) { Sf[j] = 0.f; Ss[j] = 0.f; }

    __shared__ float ks[DKH], qs[DKH];

    const size_t base = (size_t)(b * SEQ) * DMODEL + h * DKH + lane;
    const int bbase = b * SEQ * HEADS + h;

    for (int t = 0; t < SEQ; t++) {
        size_t idx = base + (size_t)t * DMODEL;
        float qv = g_q[idx];
        float kv = g_k[idx];
        float vv = g_v[idx];
        float bt = g_beta[bbase + t * HEADS];

        ks[lane] = kv;
        qs[lane] = qv;
        __syncwarp();

        float pf0 = 0.f, pf1 = 0.f, ps0 = 0.f, ps1 = 0.f;
#pragma unroll
        for (int j = 0; j < DKH; j += 2) {
            float k0 = ks[j], k1 = ks[j + 1];
            pf0 += k0 * Sf[j]; pf1 += k1 * Sf[j + 1];
            ps0 += k0 * Ss[j]; ps1 += k1 * Ss[j + 1];
        }
        float pf = pf0 + pf1, ps = ps0 + ps1;
        float cf = bt * (vv - pf);
        float cs = bt * (vv - ps);

        float of0 = 0.f, of1 = 0.f, os0 = 0.f, os1 = 0.f;
#pragma unroll
        for (int j = 0; j < DKH; j += 2) {
            float k0 = ks[j], k1 = ks[j + 1];
            float q0 = qs[j], q1 = qs[j + 1];
            Sf[j]     = gf * Sf[j]     + k0 * cf;
            Sf[j + 1] = gf * Sf[j + 1] + k1 * cf;
            Ss[j]     = gs * Ss[j]     + k0 * cs;
            Ss[j + 1] = gs * Ss[j + 1] + k1 * cs;
            of0 += q0 * Sf[j]; of1 += q1 * Sf[j + 1];
            os0 += q0 * Ss[j]; os1 += q1 * Ss[j + 1];
        }
        g_o[idx] = 0.5f * (of0 + of1 + os0 + os1);
        __syncwarp();
    }
}

// ---------------- masked mean pool + l2 normalize ----------------
__global__ void pool_kernel(const float* __restrict__ mask, float* __restrict__ out) {
    int b = blockIdx.x;
    int d = threadIdx.x;        // 384 threads
    __shared__ float red[12];

    float s = 0.f, msum = 0.f;
    for (int l = 0; l < SEQ; l++) {
        float mv = mask[b * SEQ + l];
        s += g_x[(size_t)(b * SEQ + l) * DMODEL + d] * mv;
        msum += mv;
    }
    float emb = s / fmaxf(msum, 1e-9f);

    float ss = warpSum(emb * emb);
    if ((d & 31) == 0) red[d >> 5] = ss;
    __syncthreads();
    float tot = 0.f;
#pragma unroll
    for (int w = 0; w < 12; w++) tot += red[w];
    float n = fmaxf(sqrtf(tot), 1e-12f);
    out[b * DMODEL + d] = emb / n;
}

// ---------------- launch ----------------
extern "C" void kernel_launch(void* const* d_in, const int* in_sizes, int n_in,
                              void* d_out, int out_size) {
    const int*   input_ids = (const int*)  d_in[0];
    const float* attn_mask = (const float*)d_in[1];
    const float* word_emb  = (const float*)d_in[2];
    const float* pos_emb   = (const float*)d_in[3];
    const float* type_emb  = (const float*)d_in[4];
    const float* emb_ln_g  = (const float*)d_in[5];
    const float* emb_ln_b  = (const float*)d_in[6];
    const float* Wq  = (const float*)d_in[7];
    const float* bq  = (const float*)d_in[8];
    const float* Wk  = (const float*)d_in[9];
    const float* bk  = (const float*)d_in[10];
    const float* Wv  = (const float*)d_in[11];
    const float* bv  = (const float*)d_in[12];
    const float* Wb  = (const float*)d_in[13];
    const float* dfa = (const float*)d_in[14];
    const float* dsl = (const float*)d_in[15];
    const float* Wo  = (const float*)d_in[16];
    const float* bo  = (const float*)d_in[17];
    const float* ln1g = (const float*)d_in[18];
    const float* ln1b = (const float*)d_in[19];
    const float* W1  = (const float*)d_in[20];
    const float* b1  = (const float*)d_in[21];
    const float* W2  = (const float*)d_in[22];
    const float* b2  = (const float*)d_in[23];
    const float* ln2g = (const float*)d_in[24];
    const float* ln2b = (const float*)d_in[25];
    float* out = (float*)d_out;

    float *px, *pq, *pk, *pv, *po, *pt, *ph;
    cudaGetSymbolAddress((void**)&px, g_x);
    cudaGetSymbolAddress((void**)&pq, g_q);
    cudaGetSymbolAddress((void**)&pk, g_k);
    cudaGetSymbolAddress((void**)&pv, g_v);
    cudaGetSymbolAddress((void**)&po, g_o);
    cudaGetSymbolAddress((void**)&pt, g_t);
    cudaGetSymbolAddress((void**)&ph, g_h);

    embed_ln_kernel<<<NTOK, 128>>>(input_ids, word_emb, pos_emb, type_emb, emb_ln_g, emb_ln_b);

    dim3 gProj(DMODEL / 128, NTOK / 128);   // (3,256)
    dim3 gFF1(DFF / 128, NTOK / 128);       // (12,256)

    for (int i = 0; i < NLAYER; i++) {
        const float* Wqi = Wq + (size_t)i * DMODEL * DMODEL;
        const float* Wki = Wk + (size_t)i * DMODEL * DMODEL;
        const float* Wvi = Wv + (size_t)i * DMODEL * DMODEL;
        const float* Woi = Wo + (size_t)i * DMODEL * DMODEL;
        const float* W1i = W1 + (size_t)i * DMODEL * DFF;
        const float* W2i = W2 + (size_t)i * DFF * DMODEL;

        sgemm_kernel<0><<<gProj, 256>>>(px, Wqi, bq + i * DMODEL, pq, NTOK, DMODEL, DMODEL);
        sgemm_kernel<0><<<gProj, 256>>>(px, Wki, bk + i * DMODEL, pk, NTOK, DMODEL, DMODEL);
        sgemm_kernel<0><<<gProj, 256>>>(px, Wvi, bv + i * DMODEL, pv, NTOK, DMODEL, DMODEL);
        beta_kernel<<<NTOK, 384>>>(px, Wb + (size_t)i * DMODEL * HEADS, attn_mask);

        qknorm_kernel<<<NTOK, 384>>>(pq, attn_mask, 0);
        qknorm_kernel<<<NTOK, 384>>>(pk, attn_mask, 1);

        delta_kernel<<<BATCH * HEADS, 32>>>(dfa, dsl, i);

        sgemm_kernel<0><<<gProj, 256>>>(po, Woi, bo + i * DMODEL, pt, NTOK, DMODEL, DMODEL);
        add_ln_kernel<<<NTOK, 128>>>(px, pt, ln1g + i * DMODEL, ln1b + i * DMODEL);

        sgemm_kernel<1><<<gFF1, 256>>>(px, W1i, b1 + i * DFF, ph, NTOK, DFF, DMODEL);
        sgemm_kernel<0><<<gProj, 256>>>(ph, W2i, b2 + i * DMODEL, pt, NTOK, DMODEL, DFF);
        add_ln_kernel<<<NTOK, 128>>>(px, pt, ln2g + i * DMODEL, ln2b + i * DMODEL);
    }

    pool_kernel<<<BATCH, 384>>>(attn_mask, out);
}

// round 3
// speedup vs baseline: 1.5409x; 1.5409x over previous
#include <cuda_runtime.h>
#include <math.h>

#define NLAYER 6
#define HEADS  12
#define DMODEL 384
#define DKH    32
#define DFF    1536
#define SEQ    512
#define BATCH  64
#define NTOK   (BATCH*SEQ)   /* 32768 */

// ---------------- scratch (device globals; no allocs allowed) ----------------
__device__ float g_x[NTOK*DMODEL];
__device__ float g_q[NTOK*DMODEL];
__device__ float g_k[NTOK*DMODEL];
__device__ float g_v[NTOK*DMODEL];
__device__ float g_o[NTOK*DMODEL];
__device__ float g_t[NTOK*DMODEL];
__device__ float g_beta[NTOK*HEADS];
__device__ float g_h[NTOK*DFF];

// ---------------- helpers ----------------
__device__ __forceinline__ float warpSum(float v) {
#pragma unroll
    for (int o = 16; o > 0; o >>= 1) v += __shfl_xor_sync(0xffffffffu, v, o);
    return v;
}

__device__ __forceinline__ float gelu_t(float x) {
    float u = 0.7978845608028654f * (x + 0.044715f * x * x * x);
    return 0.5f * x * (1.0f + tanhf(u));
}

__device__ __forceinline__ float sigm(float x) {
    return 1.0f / (1.0f + expf(-x));
}

__device__ __forceinline__ float to_tf32(float x) {
    unsigned u;
    asm("cvt.rna.tf32.f32 %0, %1;" : "=r"(u) : "f"(x));
    return __uint_as_float(u);
}

__device__ __forceinline__ float4 cvt4(float4 a) {
    float4 r;
    r.x = to_tf32(a.x); r.y = to_tf32(a.y);
    r.z = to_tf32(a.z); r.w = to_tf32(a.w);
    return r;
}

__device__ __forceinline__ void mma_tf32(float* d, const float* a, const float* b) {
    asm volatile(
        "mma.sync.aligned.m16n8k8.row.col.f32.tf32.tf32.f32 "
        "{%0,%1,%2,%3}, {%4,%5,%6,%7}, {%8,%9}, {%0,%1,%2,%3};\n"
        : "+f"(d[0]), "+f"(d[1]), "+f"(d[2]), "+f"(d[3])
        : "r"(__float_as_uint(a[0])), "r"(__float_as_uint(a[1])),
          "r"(__float_as_uint(a[2])), "r"(__float_as_uint(a[3])),
          "r"(__float_as_uint(b[0])), "r"(__float_as_uint(b[1])));
}

// ---------------- embedding + layernorm ----------------
__global__ void embed_ln_kernel(const int* __restrict__ ids,
                                const float* __restrict__ we,
                                const float* __restrict__ pe,
                                const float* __restrict__ te,
                                const float* __restrict__ g,
                                const float* __restrict__ bta) {
    int token = blockIdx.x;
    int l = token & (SEQ - 1);
    int id = ids[token];
    int tid = threadIdx.x;
    __shared__ float red[4];

    float v[3];
    float s = 0.f;
#pragma unroll
    for (int j = 0; j < 3; j++) {
        int d = tid + j * 128;
        float val = we[id * DMODEL + d] + pe[l * DMODEL + d] + te[d];
        v[j] = val; s += val;
    }
    s = warpSum(s);
    if ((tid & 31) == 0) red[tid >> 5] = s;
    __syncthreads();
    float mean = (red[0] + red[1] + red[2] + red[3]) * (1.0f / DMODEL);
    float s2 = 0.f;
#pragma unroll
    for (int j = 0; j < 3; j++) { float d0 = v[j] - mean; s2 += d0 * d0; }
    s2 = warpSum(s2);
    __syncthreads();
    if ((tid & 31) == 0) red[tid >> 5] = s2;
    __syncthreads();
    float var = (red[0] + red[1] + red[2] + red[3]) * (1.0f / DMODEL);
    float inv = rsqrtf(var + 1e-12f);
#pragma unroll
    for (int j = 0; j < 3; j++) {
        int d = tid + j * 128;
        g_x[token * DMODEL + d] = (v[j] - mean) * inv * g[d] + bta[d];
    }
}

// ---------------- residual add + layernorm (in-place on x) ----------------
__global__ void add_ln_kernel(float* __restrict__ x,
                              const float* __restrict__ t,
                              const float* __restrict__ g,
                              const float* __restrict__ bta) {
    int token = blockIdx.x;
    int tid = threadIdx.x;
    __shared__ float red[4];
    float v[3];
    float s = 0.f;
#pragma unroll
    for (int j = 0; j < 3; j++) {
        int d = tid + j * 128;
        float val = x[token * DMODEL + d] + t[token * DMODEL + d];
        v[j] = val; s += val;
    }
    s = warpSum(s);
    if ((tid & 31) == 0) red[tid >> 5] = s;
    __syncthreads();
    float mean = (red[0] + red[1] + red[2] + red[3]) * (1.0f / DMODEL);
    float s2 = 0.f;
#pragma unroll
    for (int j = 0; j < 3; j++) { float d0 = v[j] - mean; s2 += d0 * d0; }
    s2 = warpSum(s2);
    __syncthreads();
    if ((tid & 31) == 0) red[tid >> 5] = s2;
    __syncthreads();
    float var = (red[0] + red[1] + red[2] + red[3]) * (1.0f / DMODEL);
    float inv = rsqrtf(var + 1e-12f);
#pragma unroll
    for (int j = 0; j < 3; j++) {
        int d = tid + j * 128;
        x[token * DMODEL + d] = (v[j] - mean) * inv * g[d] + bta[d];
    }
}

// ---------------- TF32 tensor-core GEMM ----------------
// C[M,N] = A[M,K] @ B[K,N] + bias, optional double-gelu epilogue.
// BM=128 BN=128 BK=16, 256 threads (8 warps, 2x4), warp tile 64x32,
// m16n8k8 tf32 MMA, double-buffered SMEM, register-staged loads with cvt.rna.
template<int EPI>
__global__ void __launch_bounds__(256, 1) tf32_gemm_kernel(
        const float* __restrict__ A, const float* __restrict__ B,
        const float* __restrict__ bias, float* __restrict__ C,
        int M, int N, int K) {
    const int BM = 128, BN = 128, BK = 16;
    __shared__ float As[2][4][BM][4];     // [buf][kchunk][m][k%4]   8KB/buf
    __shared__ float Bs[2][BK][BN + 8];   // [buf][k][n] padded      8.7KB/buf

    const int tid  = threadIdx.x;
    const int lane = tid & 31;
    const int wid  = tid >> 5;
    const int tig  = lane & 3;      // thread-in-group (k / col pair index)
    const int grp  = lane >> 2;     // group id (row / col index)
    const int wm   = (wid & 1) * 64;
    const int wn   = (wid >> 1) * 32;
    const int bm   = blockIdx.y * BM;
    const int bn   = blockIdx.x * BN;

    float acc[4][4][4];
#pragma unroll
    for (int im = 0; im < 4; im++)
#pragma unroll
        for (int in_ = 0; in_ < 4; in_++)
#pragma unroll
            for (int r = 0; r < 4; r++) acc[im][in_][r] = 0.f;

    const int nk = K / BK;

    // ---- prologue: load tile 0 ----
    float4 aReg[2], bReg[2];
#pragma unroll
    for (int it = 0; it < 2; it++) {
        int f = tid + it * 256;                 // 0..511
        int m = f & 127, c = f >> 7;            // A: row, k-chunk
        aReg[it] = *(const float4*)(A + (size_t)(bm + m) * K + 4 * c);
        int kk = f >> 5, n4 = (f & 31) * 4;     // B: k row, col
        bReg[it] = *(const float4*)(B + (size_t)kk * N + bn + n4);
    }
#pragma unroll
    for (int it = 0; it < 2; it++) {
        int f = tid + it * 256;
        int m = f & 127, c = f >> 7;
        *(float4*)&As[0][c][m][0] = cvt4(aReg[it]);
        int kk = f >> 5, n4 = (f & 31) * 4;
        *(float4*)&Bs[0][kk][n4] = cvt4(bReg[it]);
    }
    __syncthreads();

    for (int kt = 0; kt < nk; kt++) {
        const int cur = kt & 1;
        // ---- prefetch next tile into registers ----
        if (kt + 1 < nk) {
            int k0n = (kt + 1) * BK;
#pragma unroll
            for (int it = 0; it < 2; it++) {
                int f = tid + it * 256;
                int m = f & 127, c = f >> 7;
                aReg[it] = *(const float4*)(A + (size_t)(bm + m) * K + k0n + 4 * c);
                int kk = f >> 5, n4 = (f & 31) * 4;
                bReg[it] = *(const float4*)(B + (size_t)(k0n + kk) * N + bn + n4);
            }
        }
        // ---- compute on current buffer ----
#pragma unroll
        for (int ks = 0; ks < 2; ks++) {
            float a[4][4], b[4][2];
#pragma unroll
            for (int im = 0; im < 4; im++) {
                int m = wm + im * 16 + grp;
                a[im][0] = As[cur][2 * ks][m][tig];
                a[im][1] = As[cur][2 * ks][m + 8][tig];
                a[im][2] = As[cur][2 * ks + 1][m][tig];
                a[im][3] = As[cur][2 * ks + 1][m + 8][tig];
            }
#pragma unroll
            for (int in_ = 0; in_ < 4; in_++) {
                int n = wn + in_ * 8 + grp;
                b[in_][0] = Bs[cur][ks * 8 + tig][n];
                b[in_][1] = Bs[cur][ks * 8 + tig + 4][n];
            }
#pragma unroll
            for (int im = 0; im < 4; im++)
#pragma unroll
                for (int in_ = 0; in_ < 4; in_++)
                    mma_tf32(acc[im][in_], a[im], b[in_]);
        }
        // ---- store prefetched tile to other buffer ----
        if (kt + 1 < nk) {
            int nxt = cur ^ 1;
#pragma unroll
            for (int it = 0; it < 2; it++) {
                int f = tid + it * 256;
                int m = f & 127, c = f >> 7;
                *(float4*)&As[nxt][c][m][0] = cvt4(aReg[it]);
                int kk = f >> 5, n4 = (f & 31) * 4;
                *(float4*)&Bs[nxt][kk][n4] = cvt4(bReg[it]);
            }
        }
        __syncthreads();
    }

    // ---- epilogue: bias (+ optional double-gelu), float2 stores ----
#pragma unroll
    for (int im = 0; im < 4; im++) {
        int row0 = bm + wm + im * 16 + grp;
#pragma unroll
        for (int in_ = 0; in_ < 4; in_++) {
            int col = bn + wn + in_ * 8 + 2 * tig;
            float b0 = bias[col], b1 = bias[col + 1];
            float v0 = acc[im][in_][0] + b0;
            float v1 = acc[im][in_][1] + b1;
            float v2 = acc[im][in_][2] + b0;
            float v3 = acc[im][in_][3] + b1;
            if (EPI == 1) {
                v0 = gelu_t(gelu_t(v0)); v1 = gelu_t(gelu_t(v1));
                v2 = gelu_t(gelu_t(v2)); v3 = gelu_t(gelu_t(v3));
            }
            *(float2*)&C[(size_t)row0 * N + col]       = make_float2(v0, v1);
            *(float2*)&C[(size_t)(row0 + 8) * N + col] = make_float2(v2, v3);
        }
    }
}

// ---------------- per-(token,head) l2 norm (+ optional mask multiply) ----------------
__global__ void qknorm_kernel(float* __restrict__ t, const float* __restrict__ mask, int use_mask) {
    int token = blockIdx.x;
    int h = threadIdx.x >> 5;
    int lane = threadIdx.x & 31;
    int idx = token * DMODEL + h * DKH + lane;
    float val = t[idx];
    float ss = warpSum(val * val);
    float inv = 1.0f / (sqrtf(ss) + 1e-6f);
    float m = use_mask ? mask[token] : 1.0f;
    t[idx] = val * inv * m;
}

// ---------------- beta = sigmoid(x @ Wb) * mask ----------------
__global__ void beta_kernel(const float* __restrict__ x, const float* __restrict__ Wb,
                            const float* __restrict__ mask) {
    int token = blockIdx.x;
    int h = threadIdx.x >> 5;
    int lane = threadIdx.x & 31;
    const float* xr = x + (size_t)token * DMODEL;
    float s = 0.f;
#pragma unroll
    for (int k = lane; k < DMODEL; k += 32) s += xr[k] * Wb[k * HEADS + h];
    s = warpSum(s);
    if (lane == 0) g_beta[token * HEADS + h] = sigm(s) * mask[token];
}

// ---------------- delta recurrence: one warp per (b,h), prefetched ----------------
__global__ void delta_kernel(const float* __restrict__ decay_f,
                             const float* __restrict__ decay_s,
                             int layer) {
    int bh = blockIdx.x;
    int b = bh / HEADS;
    int h = bh % HEADS;
    int lane = threadIdx.x;

    float gf = sigm(decay_f[layer * HEADS + h]);
    float gs = sigm(decay_s[layer * HEADS + h]);

    float Sf[DKH], Ss[DKH];
#pragma unroll
    for (int j = 0; j < DKH; j++) { Sf[j] = 0.f; Ss[j] = 0.f; }

    __shared__ float ks[DKH], qs[DKH];

    const size_t base = (size_t)(b * SEQ) * DMODEL + h * DKH + lane;
    const int bbase = b * SEQ * HEADS + h;

    // prefetch t=0
    float qn = g_q[base], kn = g_k[base], vn = g_v[base];
    float btn = g_beta[bbase];

    for (int t = 0; t < SEQ; t++) {
        float qv = qn, kv = kn, vv = vn, bt = btn;
        if (t + 1 < SEQ) {
            size_t idn = base + (size_t)(t + 1) * DMODEL;
            qn = g_q[idn]; kn = g_k[idn]; vn = g_v[idn];
            btn = g_beta[bbase + (t + 1) * HEADS];
        }

        ks[lane] = kv;
        qs[lane] = qv;
        __syncwarp();

        float pf0 = 0.f, pf1 = 0.f, ps0 = 0.f, ps1 = 0.f;
#pragma unroll
        for (int j = 0; j < DKH; j += 2) {
            float k0 = ks[j], k1 = ks[j + 1];
            pf0 += k0 * Sf[j]; pf1 += k1 * Sf[j + 1];
            ps0 += k0 * Ss[j]; ps1 += k1 * Ss[j + 1];
        }
        float pf = pf0 + pf1, ps = ps0 + ps1;
        float cf = bt * (vv - pf);
        float cs = bt * (vv - ps);

        float of0 = 0.f, of1 = 0.f, os0 = 0.f, os1 = 0.f;
#pragma unroll
        for (int j = 0; j < DKH; j += 2) {
            float k0 = ks[j], k1 = ks[j + 1];
            float q0 = qs[j], q1 = qs[j + 1];
            Sf[j]     = gf * Sf[j]     + k0 * cf;
            Sf[j + 1] = gf * Sf[j + 1] + k1 * cf;
            Ss[j]     = gs * Ss[j]     + k0 * cs;
            Ss[j + 1] = gs * Ss[j + 1] + k1 * cs;
            of0 += q0 * Sf[j]; of1 += q1 * Sf[j + 1];
            os0 += q0 * Ss[j]; os1 += q1 * Ss[j + 1];
        }
        g_o[base + (size_t)t * DMODEL] = 0.5f * (of0 + of1 + os0 + os1);
        __syncwarp();
    }
}

// ---------------- masked mean pool + l2 normalize ----------------
__global__ void pool_kernel(const float* __restrict__ mask, float* __restrict__ out) {
    int b = blockIdx.x;
    int d = threadIdx.x;        // 384 threads
    __shared__ float red[12];

    float s = 0.f, msum = 0.f;
    for (int l = 0; l < SEQ; l++) {
        float mv = mask[b * SEQ + l];
        s += g_x[(size_t)(b * SEQ + l) * DMODEL + d] * mv;
        msum += mv;
    }
    float emb = s / fmaxf(msum, 1e-9f);

    float ss = warpSum(emb * emb);
    if ((d & 31) == 0) red[d >> 5] = ss;
    __syncthreads();
    float tot = 0.f;
#pragma unroll
    for (int w = 0; w < 12; w++) tot += red[w];
    float n = fmaxf(sqrtf(tot), 1e-12f);
    out[b * DMODEL + d] = emb / n;
}

// ---------------- launch ----------------
extern "C" void kernel_launch(void* const* d_in, const int* in_sizes, int n_in,
                              void* d_out, int out_size) {
    const int*   input_ids = (const int*)  d_in[0];
    const float* attn_mask = (const float*)d_in[1];
    const float* word_emb  = (const float*)d_in[2];
    const float* pos_emb   = (const float*)d_in[3];
    const float* type_emb  = (const float*)d_in[4];
    const float* emb_ln_g  = (const float*)d_in[5];
    const float* emb_ln_b  = (const float*)d_in[6];
    const float* Wq  = (const float*)d_in[7];
    const float* bq  = (const float*)d_in[8];
    const float* Wk  = (const float*)d_in[9];
    const float* bk  = (const float*)d_in[10];
    const float* Wv  = (const float*)d_in[11];
    const float* bv  = (const float*)d_in[12];
    const float* Wb  = (const float*)d_in[13];
    const float* dfa = (const float*)d_in[14];
    const float* dsl = (const float*)d_in[15];
    const float* Wo  = (const float*)d_in[16];
    const float* bo  = (const float*)d_in[17];
    const float* ln1g = (const float*)d_in[18];
    const float* ln1b = (const float*)d_in[19];
    const float* W1  = (const float*)d_in[20];
    const float* b1  = (const float*)d_in[21];
    const float* W2  = (const float*)d_in[22];
    const float* b2  = (const float*)d_in[23];
    const float* ln2g = (const float*)d_in[24];
    const float* ln2b = (const float*)d_in[25];
    float* out = (float*)d_out;

    float *px, *pq, *pk, *pv, *po, *pt, *ph;
    cudaGetSymbolAddress((void**)&px, g_x);
    cudaGetSymbolAddress((void**)&pq, g_q);
    cudaGetSymbolAddress((void**)&pk, g_k);
    cudaGetSymbolAddress((void**)&pv, g_v);
    cudaGetSymbolAddress((void**)&po, g_o);
    cudaGetSymbolAddress((void**)&pt, g_t);
    cudaGetSymbolAddress((void**)&ph, g_h);

    embed_ln_kernel<<<NTOK, 128>>>(input_ids, word_emb, pos_emb, type_emb, emb_ln_g, emb_ln_b);

    dim3 gProj(DMODEL / 128, NTOK / 128);   // (3,256)
    dim3 gFF1(DFF / 128, NTOK / 128);       // (12,256)

    for (int i = 0; i < NLAYER; i++) {
        const float* Wqi = Wq + (size_t)i * DMODEL * DMODEL;
        const float* Wki = Wk + (size_t)i * DMODEL * DMODEL;
        const float* Wvi = Wv + (size_t)i * DMODEL * DMODEL;
        const float* Woi = Wo + (size_t)i * DMODEL * DMODEL;
        const float* W1i = W1 + (size_t)i * DMODEL * DFF;
        const float* W2i = W2 + (size_t)i * DFF * DMODEL;

        tf32_gemm_kernel<0><<<gProj, 256>>>(px, Wqi, bq + i * DMODEL, pq, NTOK, DMODEL, DMODEL);
        tf32_gemm_kernel<0><<<gProj, 256>>>(px, Wki, bk + i * DMODEL, pk, NTOK, DMODEL, DMODEL);
        tf32_gemm_kernel<0><<<gProj, 256>>>(px, Wvi, bv + i * DMODEL, pv, NTOK, DMODEL, DMODEL);
        beta_kernel<<<NTOK, 384>>>(px, Wb + (size_t)i * DMODEL * HEADS, attn_mask);

        qknorm_kernel<<<NTOK, 384>>>(pq, attn_mask, 0);
        qknorm_kernel<<<NTOK, 384>>>(pk, attn_mask, 1);

        delta_kernel<<<BATCH * HEADS, 32>>>(dfa, dsl, i);

        tf32_gemm_kernel<0><<<gProj, 256>>>(po, Woi, bo + i * DMODEL, pt, NTOK, DMODEL, DMODEL);
        add_ln_kernel<<<NTOK, 128>>>(px, pt, ln1g + i * DMODEL, ln1b + i * DMODEL);

        tf32_gemm_kernel<1><<<gFF1, 256>>>(px, W1i, b1 + i * DFF, ph, NTOK, DFF, DMODEL);
        tf32_gemm_kernel<0><<<gProj, 256>>>(ph, W2i, b2 + i * DMODEL, pt, NTOK, DMODEL, DFF);
        add_ln_kernel<<<NTOK, 128>>>(px, pt, ln2g + i * DMODEL, ln2b + i * DMODEL);
    }

    pool_kernel<<<BATCH, 384>>>(attn_mask, out);
}

// round 4
// speedup vs baseline: 1.5416x; 1.0005x over previous
#include <cuda_runtime.h>
#include <math.h>

#define NLAYER 6
#define HEADS  12
#define DMODEL 384
#define DKH    32
#define DFF    1536
#define SEQ    512
#define BATCH  64
#define NTOK   (BATCH*SEQ)   /* 32768 */

// ---------------- scratch (device globals; no allocs allowed) ----------------
__device__ float g_x[NTOK*DMODEL];
__device__ float g_q[NTOK*DMODEL];
__device__ float g_k[NTOK*DMODEL];
__device__ float g_v[NTOK*DMODEL];
__device__ float g_o[NTOK*DMODEL];
__device__ float g_t[NTOK*DMODEL];
__device__ float g_beta[NTOK*HEADS];
__device__ float g_h[NTOK*DFF];

// ---------------- helpers ----------------
__device__ __forceinline__ float warpSum(float v) {
#pragma unroll
    for (int o = 16; o > 0; o >>= 1) v += __shfl_xor_sync(0xffffffffu, v, o);
    return v;
}

__device__ __forceinline__ float gelu_t(float x) {
    float u = 0.7978845608028654f * (x + 0.044715f * x * x * x);
    return 0.5f * x * (1.0f + tanhf(u));
}

__device__ __forceinline__ float sigm(float x) {
    return 1.0f / (1.0f + expf(-x));
}

__device__ __forceinline__ float to_tf32(float x) {
    unsigned u;
    asm("cvt.rna.tf32.f32 %0, %1;" : "=r"(u) : "f"(x));
    return __uint_as_float(u);
}

__device__ __forceinline__ float4 cvt4(float4 a) {
    float4 r;
    r.x = to_tf32(a.x); r.y = to_tf32(a.y);
    r.z = to_tf32(a.z); r.w = to_tf32(a.w);
    return r;
}

__device__ __forceinline__ void mma_tf32(float* d, const float* a, const float* b) {
    asm volatile(
        "mma.sync.aligned.m16n8k8.row.col.f32.tf32.tf32.f32 "
        "{%0,%1,%2,%3}, {%4,%5,%6,%7}, {%8,%9}, {%0,%1,%2,%3};\n"
        : "+f"(d[0]), "+f"(d[1]), "+f"(d[2]), "+f"(d[3])
        : "r"(__float_as_uint(a[0])), "r"(__float_as_uint(a[1])),
          "r"(__float_as_uint(a[2])), "r"(__float_as_uint(a[3])),
          "r"(__float_as_uint(b[0])), "r"(__float_as_uint(b[1])));
}

// ---------------- embedding + layernorm ----------------
__global__ void embed_ln_kernel(const int* __restrict__ ids,
                                const float* __restrict__ we,
                                const float* __restrict__ pe,
                                const float* __restrict__ te,
                                const float* __restrict__ g,
                                const float* __restrict__ bta) {
    int token = blockIdx.x;
    int l = token & (SEQ - 1);
    int id = ids[token];
    int tid = threadIdx.x;
    __shared__ float red[4];

    float v[3];
    float s = 0.f;
#pragma unroll
    for (int j = 0; j < 3; j++) {
        int d = tid + j * 128;
        float val = we[id * DMODEL + d] + pe[l * DMODEL + d] + te[d];
        v[j] = val; s += val;
    }
    s = warpSum(s);
    if ((tid & 31) == 0) red[tid >> 5] = s;
    __syncthreads();
    float mean = (red[0] + red[1] + red[2] + red[3]) * (1.0f / DMODEL);
    float s2 = 0.f;
#pragma unroll
    for (int j = 0; j < 3; j++) { float d0 = v[j] - mean; s2 += d0 * d0; }
    s2 = warpSum(s2);
    __syncthreads();
    if ((tid & 31) == 0) red[tid >> 5] = s2;
    __syncthreads();
    float var = (red[0] + red[1] + red[2] + red[3]) * (1.0f / DMODEL);
    float inv = rsqrtf(var + 1e-12f);
#pragma unroll
    for (int j = 0; j < 3; j++) {
        int d = tid + j * 128;
        g_x[token * DMODEL + d] = (v[j] - mean) * inv * g[d] + bta[d];
    }
}

// ---------------- residual add + layernorm (in-place on x) ----------------
__global__ void add_ln_kernel(float* __restrict__ x,
                              const float* __restrict__ t,
                              const float* __restrict__ g,
                              const float* __restrict__ bta) {
    int token = blockIdx.x;
    int tid = threadIdx.x;
    __shared__ float red[4];
    float v[3];
    float s = 0.f;
#pragma unroll
    for (int j = 0; j < 3; j++) {
        int d = tid + j * 128;
        float val = x[token * DMODEL + d] + t[token * DMODEL + d];
        v[j] = val; s += val;
    }
    s = warpSum(s);
    if ((tid & 31) == 0) red[tid >> 5] = s;
    __syncthreads();
    float mean = (red[0] + red[1] + red[2] + red[3]) * (1.0f / DMODEL);
    float s2 = 0.f;
#pragma unroll
    for (int j = 0; j < 3; j++) { float d0 = v[j] - mean; s2 += d0 * d0; }
    s2 = warpSum(s2);
    __syncthreads();
    if ((tid & 31) == 0) red[tid >> 5] = s2;
    __syncthreads();
    float var = (red[0] + red[1] + red[2] + red[3]) * (1.0f / DMODEL);
    float inv = rsqrtf(var + 1e-12f);
#pragma unroll
    for (int j = 0; j < 3; j++) {
        int d = tid + j * 128;
        x[token * DMODEL + d] = (v[j] - mean) * inv * g[d] + bta[d];
    }
}

// ---------------- TF32 tensor-core GEMM ----------------
// C[M,N] = A[M,K] @ B[K,N] + bias, optional double-gelu epilogue.
// BM=128 BN=128 BK=16, 256 threads (8 warps, 2x4), warp tile 64x32,
// m16n8k8 tf32 MMA, double-buffered SMEM, register-staged loads with cvt.rna.
template<int EPI>
__global__ void __launch_bounds__(256, 1) tf32_gemm_kernel(
        const float* __restrict__ A, const float* __restrict__ B,
        const float* __restrict__ bias, float* __restrict__ C,
        int M, int N, int K) {
    const int BM = 128, BN = 128, BK = 16;
    __shared__ float As[2][4][BM][4];     // [buf][kchunk][m][k%4]   8KB/buf
    __shared__ float Bs[2][BK][BN + 8];   // [buf][k][n] padded      8.7KB/buf

    const int tid  = threadIdx.x;
    const int lane = tid & 31;
    const int wid  = tid >> 5;
    const int tig  = lane & 3;      // thread-in-group (k / col pair index)
    const int grp  = lane >> 2;     // group id (row / col index)
    const int wm   = (wid & 1) * 64;
    const int wn   = (wid >> 1) * 32;
    const int bm   = blockIdx.y * BM;
    const int bn   = blockIdx.x * BN;

    float acc[4][4][4];
#pragma unroll
    for (int im = 0; im < 4; im++)
#pragma unroll
        for (int in_ = 0; in_ < 4; in_++)
#pragma unroll
            for (int r = 0; r < 4; r++) acc[im][in_][r] = 0.f;

    const int nk = K / BK;

    // ---- prologue: load tile 0 ----
    float4 aReg[2], bReg[2];
#pragma unroll
    for (int it = 0; it < 2; it++) {
        int f = tid + it * 256;                 // 0..511
        int m = f & 127, c = f >> 7;            // A: row, k-chunk
        aReg[it] = *(const float4*)(A + (size_t)(bm + m) * K + 4 * c);
        int kk = f >> 5, n4 = (f & 31) * 4;     // B: k row, col
        bReg[it] = *(const float4*)(B + (size_t)kk * N + bn + n4);
    }
#pragma unroll
    for (int it = 0; it < 2; it++) {
        int f = tid + it * 256;
        int m = f & 127, c = f >> 7;
        *(float4*)&As[0][c][m][0] = cvt4(aReg[it]);
        int kk = f >> 5, n4 = (f & 31) * 4;
        *(float4*)&Bs[0][kk][n4] = cvt4(bReg[it]);
    }
    __syncthreads();

    for (int kt = 0; kt < nk; kt++) {
        const int cur = kt & 1;
        // ---- prefetch next tile into registers ----
        if (kt + 1 < nk) {
            int k0n = (kt + 1) * BK;
#pragma unroll
            for (int it = 0; it < 2; it++) {
                int f = tid + it * 256;
                int m = f & 127, c = f >> 7;
                aReg[it] = *(const float4*)(A + (size_t)(bm + m) * K + k0n + 4 * c);
                int kk = f >> 5, n4 = (f & 31) * 4;
                bReg[it] = *(const float4*)(B + (size_t)(k0n + kk) * N + bn + n4);
            }
        }
        // ---- compute on current buffer ----
#pragma unroll
        for (int ks = 0; ks < 2; ks++) {
            float a[4][4], b[4][2];
#pragma unroll
            for (int im = 0; im < 4; im++) {
                int m = wm + im * 16 + grp;
                a[im][0] = As[cur][2 * ks][m][tig];
                a[im][1] = As[cur][2 * ks][m + 8][tig];
                a[im][2] = As[cur][2 * ks + 1][m][tig];
                a[im][3] = As[cur][2 * ks + 1][m + 8][tig];
            }
#pragma unroll
            for (int in_ = 0; in_ < 4; in_++) {
                int n = wn + in_ * 8 + grp;
                b[in_][0] = Bs[cur][ks * 8 + tig][n];
                b[in_][1] = Bs[cur][ks * 8 + tig + 4][n];
            }
#pragma unroll
            for (int im = 0; im < 4; im++)
#pragma unroll
                for (int in_ = 0; in_ < 4; in_++)
                    mma_tf32(acc[im][in_], a[im], b[in_]);
        }
        // ---- store prefetched tile to other buffer ----
        if (kt + 1 < nk) {
            int nxt = cur ^ 1;
#pragma unroll
            for (int it = 0; it < 2; it++) {
                int f = tid + it * 256;
                int m = f & 127, c = f >> 7;
                *(float4*)&As[nxt][c][m][0] = cvt4(aReg[it]);
                int kk = f >> 5, n4 = (f & 31) * 4;
                *(float4*)&Bs[nxt][kk][n4] = cvt4(bReg[it]);
            }
        }
        __syncthreads();
    }

    // ---- epilogue: bias (+ optional double-gelu), float2 stores ----
#pragma unroll
    for (int im = 0; im < 4; im++) {
        int row0 = bm + wm + im * 16 + grp;
#pragma unroll
        for (int in_ = 0; in_ < 4; in_++) {
            int col = bn + wn + in_ * 8 + 2 * tig;
            float b0 = bias[col], b1 = bias[col + 1];
            float v0 = acc[im][in_][0] + b0;
            float v1 = acc[im][in_][1] + b1;
            float v2 = acc[im][in_][2] + b0;
            float v3 = acc[im][in_][3] + b1;
            if (EPI == 1) {
                v0 = gelu_t(gelu_t(v0)); v1 = gelu_t(gelu_t(v1));
                v2 = gelu_t(gelu_t(v2)); v3 = gelu_t(gelu_t(v3));
            }
            *(float2*)&C[(size_t)row0 * N + col]       = make_float2(v0, v1);
            *(float2*)&C[(size_t)(row0 + 8) * N + col] = make_float2(v2, v3);
        }
    }
}

// ---------------- per-(token,head) l2 norm (+ optional mask multiply) ----------------
__global__ void qknorm_kernel(float* __restrict__ t, const float* __restrict__ mask, int use_mask) {
    int token = blockIdx.x;
    int h = threadIdx.x >> 5;
    int lane = threadIdx.x & 31;
    int idx = token * DMODEL + h * DKH + lane;
    float val = t[idx];
    float ss = warpSum(val * val);
    float inv = 1.0f / (sqrtf(ss) + 1e-6f);
    float m = use_mask ? mask[token] : 1.0f;
    t[idx] = val * inv * m;
}

// ---------------- beta = sigmoid(x @ Wb) * mask ----------------
__global__ void beta_kernel(const float* __restrict__ x, const float* __restrict__ Wb,
                            const float* __restrict__ mask) {
    int token = blockIdx.x;
    int h = threadIdx.x >> 5;
    int lane = threadIdx.x & 31;
    const float* xr = x + (size_t)token * DMODEL;
    float s = 0.f;
#pragma unroll
    for (int k = lane; k < DMODEL; k += 32) s += xr[k] * Wb[k * HEADS + h];
    s = warpSum(s);
    if (lane == 0) g_beta[token * HEADS + h] = sigm(s) * mask[token];
}

// ---------------- delta recurrence: one warp per (b,h), prefetched ----------------
__global__ void delta_kernel(const float* __restrict__ decay_f,
                             const float* __restrict__ decay_s,
                             int layer) {
    int bh = blockIdx.x;
    int b = bh / HEADS;
    int h = bh % HEADS;
    int lane = threadIdx.x;

    float gf = sigm(decay_f[layer * HEADS + h]);
    float gs = sigm(decay_s[layer * HEADS + h]);

    float Sf[DKH], Ss[DKH];
#pragma unroll
    for (int j = 0; j < DKH; j++) { Sf[j] = 0.f; Ss[j] = 0.f; }

    __shared__ float ks[DKH], qs[DKH];

    const size_t base = (size_t)(b * SEQ) * DMODEL + h * DKH + lane;
    const int bbase = b * SEQ * HEADS + h;

    // prefetch t=0
    float qn = g_q[base], kn = g_k[base], vn = g_v[base];
    float btn = g_beta[bbase];

    for (int t = 0; t < SEQ; t++) {
        float qv = qn, kv = kn, vv = vn, bt = btn;
        if (t + 1 < SEQ) {
            size_t idn = base + (size_t)(t + 1) * DMODEL;
            qn = g_q[idn]; kn = g_k[idn]; vn = g_v[idn];
            btn = g_beta[bbase + (t + 1) * HEADS];
        }

        ks[lane] = kv;
        qs[lane] = qv;
        __syncwarp();

        float pf0 = 0.f, pf1 = 0.f, ps0 = 0.f, ps1 = 0.f;
#pragma unroll
        for (int j = 0; j < DKH; j += 2) {
            float k0 = ks[j], k1 = ks[j + 1];
            pf0 += k0 * Sf[j]; pf1 += k1 * Sf[j + 1];
            ps0 += k0 * Ss[j]; ps1 += k1 * Ss[j + 1];
        }
        float pf = pf0 + pf1, ps = ps0 + ps1;
        float cf = bt * (vv - pf);
        float cs = bt * (vv - ps);

        float of0 = 0.f, of1 = 0.f, os0 = 0.f, os1 = 0.f;
#pragma unroll
        for (int j = 0; j < DKH; j += 2) {
            float k0 = ks[j], k1 = ks[j + 1];
            float q0 = qs[j], q1 = qs[j + 1];
            Sf[j]     = gf * Sf[j]     + k0 * cf;
            Sf[j + 1] = gf * Sf[j + 1] + k1 * cf;
            Ss[j]     = gs * Ss[j]     + k0 * cs;
            Ss[j + 1] = gs * Ss[j + 1] + k1 * cs;
            of0 += q0 * Sf[j]; of1 += q1 * Sf[j + 1];
            os0 += q0 * Ss[j]; os1 += q1 * Ss[j + 1];
        }
        g_o[base + (size_t)t * DMODEL] = 0.5f * (of0 + of1 + os0 + os1);
        __syncwarp();
    }
}

// ---------------- masked mean pool + l2 normalize ----------------
__global__ void pool_kernel(const float* __restrict__ mask, float* __restrict__ out) {
    int b = blockIdx.x;
    int d = threadIdx.x;        // 384 threads
    __shared__ float red[12];

    float s = 0.f, msum = 0.f;
    for (int l = 0; l < SEQ; l++) {
        float mv = mask[b * SEQ + l];
        s += g_x[(size_t)(b * SEQ + l) * DMODEL + d] * mv;
        msum += mv;
    }
    float emb = s / fmaxf(msum, 1e-9f);

    float ss = warpSum(emb * emb);
    if ((d & 31) == 0) red[d >> 5] = ss;
    __syncthreads();
    float tot = 0.f;
#pragma unroll
    for (int w = 0; w < 12; w++) tot += red[w];
    float n = fmaxf(sqrtf(tot), 1e-12f);
    out[b * DMODEL + d] = emb / n;
}

// ---------------- launch ----------------
extern "C" void kernel_launch(void* const* d_in, const int* in_sizes, int n_in,
                              void* d_out, int out_size) {
    const int*   input_ids = (const int*)  d_in[0];
    const float* attn_mask = (const float*)d_in[1];
    const float* word_emb  = (const float*)d_in[2];
    const float* pos_emb   = (const float*)d_in[3];
    const float* type_emb  = (const float*)d_in[4];
    const float* emb_ln_g  = (const float*)d_in[5];
    const float* emb_ln_b  = (const float*)d_in[6];
    const float* Wq  = (const float*)d_in[7];
    const float* bq  = (const float*)d_in[8];
    const float* Wk  = (const float*)d_in[9];
    const float* bk  = (const float*)d_in[10];
    const float* Wv  = (const float*)d_in[11];
    const float* bv  = (const float*)d_in[12];
    const float* Wb  = (const float*)d_in[13];
    const float* dfa = (const float*)d_in[14];
    const float* dsl = (const float*)d_in[15];
    const float* Wo  = (const float*)d_in[16];
    const float* bo  = (const float*)d_in[17];
    const float* ln1g = (const float*)d_in[18];
    const float* ln1b = (const float*)d_in[19];
    const float* W1  = (const float*)d_in[20];
    const float* b1  = (const float*)d_in[21];
    const float* W2  = (const float*)d_in[22];
    const float* b2  = (const float*)d_in[23];
    const float* ln2g = (const float*)d_in[24];
    const float* ln2b = (const float*)d_in[25];
    float* out = (float*)d_out;

    float *px, *pq, *pk, *pv, *po, *pt, *ph;
    cudaGetSymbolAddress((void**)&px, g_x);
    cudaGetSymbolAddress((void**)&pq, g_q);
    cudaGetSymbolAddress((void**)&pk, g_k);
    cudaGetSymbolAddress((void**)&pv, g_v);
    cudaGetSymbolAddress((void**)&po, g_o);
    cudaGetSymbolAddress((void**)&pt, g_t);
    cudaGetSymbolAddress((void**)&ph, g_h);

    embed_ln_kernel<<<NTOK, 128>>>(input_ids, word_emb, pos_emb, type_emb, emb_ln_g, emb_ln_b);

    dim3 gProj(DMODEL / 128, NTOK / 128);   // (3,256)
    dim3 gFF1(DFF / 128, NTOK / 128);       // (12,256)

    for (int i = 0; i < NLAYER; i++) {
        const float* Wqi = Wq + (size_t)i * DMODEL * DMODEL;
        const float* Wki = Wk + (size_t)i * DMODEL * DMODEL;
        const float* Wvi = Wv + (size_t)i * DMODEL * DMODEL;
        const float* Woi = Wo + (size_t)i * DMODEL * DMODEL;
        const float* W1i = W1 + (size_t)i * DMODEL * DFF;
        const float* W2i = W2 + (size_t)i * DFF * DMODEL;

        tf32_gemm_kernel<0><<<gProj, 256>>>(px, Wqi, bq + i * DMODEL, pq, NTOK, DMODEL, DMODEL);
        tf32_gemm_kernel<0><<<gProj, 256>>>(px, Wki, bk + i * DMODEL, pk, NTOK, DMODEL, DMODEL);
        tf32_gemm_kernel<0><<<gProj, 256>>>(px, Wvi, bv + i * DMODEL, pv, NTOK, DMODEL, DMODEL);
        beta_kernel<<<NTOK, 384>>>(px, Wb + (size_t)i * DMODEL * HEADS, attn_mask);

        qknorm_kernel<<<NTOK, 384>>>(pq, attn_mask, 0);
        qknorm_kernel<<<NTOK, 384>>>(pk, attn_mask, 1);

        delta_kernel<<<BATCH * HEADS, 32>>>(dfa, dsl, i);

        tf32_gemm_kernel<0><<<gProj, 256>>>(po, Woi, bo + i * DMODEL, pt, NTOK, DMODEL, DMODEL);
        add_ln_kernel<<<NTOK, 128>>>(px, pt, ln1g + i * DMODEL, ln1b + i * DMODEL);

        tf32_gemm_kernel<1><<<gFF1, 256>>>(px, W1i, b1 + i * DFF, ph, NTOK, DFF, DMODEL);
        tf32_gemm_kernel<0><<<gProj, 256>>>(ph, W2i, b2 + i * DMODEL, pt, NTOK, DMODEL, DFF);
        add_ln_kernel<<<NTOK, 128>>>(px, pt, ln2g + i * DMODEL, ln2b + i * DMODEL);
    }

    pool_kernel<<<BATCH, 384>>>(attn_mask, out);
}